// round 6
// baseline (speedup 1.0000x reference)
#include <cuda_runtime.h>
#include <cstdint>
#include <cstddef>

#define HDIM   128
#define GDIM   512      // 4*H
#define BATCH  256
#define SEQ    512
#define DIN    80
#define EMB    256
#define KREG   72       // k-rows of W_hh^T register-resident per column (36 f32x2 pairs)
#define KSP    28       // remaining (128-72)/2 = 28 k-pairs per column in shared memory
#define WSTRIDE 29      // float2 row stride (29 odd -> conflict-free LDS.64 across lanes)

typedef unsigned long long u64;

// ---------------- device scratch (no allocations allowed) ----------------
__device__ float g_G[(size_t)BATCH * SEQ * GDIM];    // gate pre-activations (input part)
__device__ float g_hout[(size_t)BATCH * SEQ * HDIM]; // per-step h_out
__device__ float g_Wc[GDIM * DIN];                   // fused  W_ih @ W_in   [512][80]
__device__ float g_bc[GDIM];                         // fused  W_ih@b_in + b_ih + b_hh
__device__ float g_WT[HDIM * GDIM];                  // W_hh^T: WT[k][j] = W_hh[j][k]
__device__ float2 g_WTp[GDIM * KSP];                 // k-pairs (72+2p,73+2p) per column j

// ---------------- f32x2 helpers ----------------
__device__ __forceinline__ void fma2(u64& d, u64 a, u64 b) {
    asm("fma.rn.f32x2 %0, %1, %2, %0;" : "+l"(d) : "l"(a), "l"(b));
}
__device__ __forceinline__ u64 pack2(float lo, float hi) {
    u64 r; asm("mov.b64 %0, {%1, %2};" : "=l"(r) : "f"(lo), "f"(hi)); return r;
}
__device__ __forceinline__ u64 dup2(float x) {
    u64 r; asm("mov.b64 %0, {%1, %1};" : "=l"(r) : "f"(x)); return r;
}
__device__ __forceinline__ float2 unpack2(u64 v) {
    float2 r; asm("mov.b64 {%0, %1}, %2;" : "=f"(r.x), "=f"(r.y) : "l"(v)); return r;
}

// ---------------- math helpers ----------------
__device__ __forceinline__ float sigf(float x) {
    float xc = fminf(fmaxf(x, -30.f), 30.f);
    return __fdividef(1.0f, 1.0f + __expf(-xc));
}
__device__ __forceinline__ float tanh_fast(float x) {
    float xc = fminf(fmaxf(x, -15.f), 15.f);
    float e = __expf(2.0f * xc);
    return 1.0f - __fdividef(2.0f, e + 1.0f);
}

// ---------------- kernel 0: fold W_in into W_ih, transpose W_hh ----------------
__global__ void combine_kernel(const float* __restrict__ W_in, const float* __restrict__ b_in,
                               const float* __restrict__ W_ih, const float* __restrict__ b_ih,
                               const float* __restrict__ W_hh, const float* __restrict__ b_hh) {
    __shared__ float wih[EMB];
    int j = blockIdx.x;           // 0..511
    int tid = threadIdx.x;        // 128 threads
    for (int e = tid; e < EMB; e += 128) wih[e] = W_ih[j * EMB + e];
    // transpose W_hh row j into column j of WT (k-major)
    g_WT[tid * GDIM + j] = W_hh[j * HDIM + tid];
    // packed k-pairs for the smem-resident tail (k in [KREG,128))
    if (tid >= KREG && !(tid & 1)) {
        g_WTp[j * KSP + ((tid - KREG) >> 1)] =
            make_float2(W_hh[j * HDIM + tid], W_hh[j * HDIM + tid + 1]);
    }
    __syncthreads();
    if (tid < DIN) {
        float s = 0.f;
        #pragma unroll 8
        for (int e = 0; e < EMB; e++) s = fmaf(wih[e], W_in[e * DIN + tid], s);
        g_Wc[j * DIN + tid] = s;
    }
    if (tid == 96) {
        float s = b_ih[j] + b_hh[j];
        #pragma unroll 8
        for (int e = 0; e < EMB; e++) s = fmaf(wih[e], b_in[e], s);
        g_bc[j] = s;
    }
}

// ---------------- kernel 1: G[m][j] = x[m][:] . Wc[j][:] + bc[j] ----------------
// M = 131072, N = 512, K = 80. BM=BN=128, 256 threads, 8x8 tile, f32x2 packed.
__global__ void __launch_bounds__(256, 2) gemm_kernel(const float* __restrict__ x) {
    __shared__ float As[40][132];  // x tile transposed   As[k][m']
    __shared__ float Bs[40][132];  // Wc tile transposed  Bs[k][n']
    __shared__ float bcs[128];

    int tid = threadIdx.x;
    int n0 = blockIdx.x * 128;
    int m0 = blockIdx.y * 128;
    if (tid < 128) bcs[tid] = g_bc[n0 + tid];
    int tr = tid >> 4, tc = tid & 15;

    u64 acc[8][4];
    #pragma unroll
    for (int i = 0; i < 8; i++)
        #pragma unroll
        for (int j = 0; j < 4; j++) acc[i][j] = 0ull;

    for (int kt = 0; kt < 2; kt++) {
        #pragma unroll
        for (int r = 0; r < 20; r++) {
            int idx = tid + r * 256;      // 0..5119
            int row = idx / 40;
            int col = idx - row * 40;
            As[col][row] = x[(size_t)(m0 + row) * DIN + kt * 40 + col];
            Bs[col][row] = g_Wc[(n0 + row) * DIN + kt * 40 + col];
        }
        __syncthreads();
        #pragma unroll 4
        for (int k = 0; k < 40; k++) {
            float4 a0 = *(const float4*)&As[k][tr * 8];
            float4 a1 = *(const float4*)&As[k][tr * 8 + 4];
            float4 b0 = *(const float4*)&Bs[k][tc * 8];
            float4 b1 = *(const float4*)&Bs[k][tc * 8 + 4];
            u64 ap[8] = {dup2(a0.x), dup2(a0.y), dup2(a0.z), dup2(a0.w),
                         dup2(a1.x), dup2(a1.y), dup2(a1.z), dup2(a1.w)};
            u64 bp[4] = {pack2(b0.x, b0.y), pack2(b0.z, b0.w),
                         pack2(b1.x, b1.y), pack2(b1.z, b1.w)};
            #pragma unroll
            for (int i = 0; i < 8; i++)
                #pragma unroll
                for (int j = 0; j < 4; j++)
                    fma2(acc[i][j], ap[i], bp[j]);
        }
        __syncthreads();
    }

    float bc0 = bcs[tc * 8 + 0], bc1 = bcs[tc * 8 + 1], bc2 = bcs[tc * 8 + 2], bc3 = bcs[tc * 8 + 3];
    float bc4 = bcs[tc * 8 + 4], bc5 = bcs[tc * 8 + 5], bc6 = bcs[tc * 8 + 6], bc7 = bcs[tc * 8 + 7];
    #pragma unroll
    for (int i = 0; i < 8; i++) {
        float* orow = g_G + (size_t)(m0 + tr * 8 + i) * GDIM + n0 + tc * 8;
        float2 v0 = unpack2(acc[i][0]), v1 = unpack2(acc[i][1]);
        float2 v2 = unpack2(acc[i][2]), v3 = unpack2(acc[i][3]);
        *(float4*)orow       = make_float4(v0.x + bc0, v0.y + bc1, v1.x + bc2, v1.y + bc3);
        *(float4*)(orow + 4) = make_float4(v2.x + bc4, v2.y + bc5, v3.x + bc6, v3.y + bc7);
    }
}

// ---------------- kernel 2: sequential LSTM recurrence + time pooling ----------------
// 128 blocks x 256 threads; block owns batch rows (2b, 2b+1) for all 512 steps.
// Thread tid owns gate columns j0=tid and j1=tid+256 (4 f32x2 accumulators).
// Per column: k in [0,72) as 36 packed f32x2 registers, k in [72,128) as 28
// packed float2 in smem (stride-29 rows -> conflict-free LDS.64).
// Halves the per-SM LDS instruction count vs the 512-thread version (the
// h-broadcast loads were replicated per warp); phase B now uses all threads.
__global__ void __launch_bounds__(256, 1) lstm_kernel(const float* __restrict__ w_time) {
    extern __shared__ float smem[];
    float* gates = smem;                       // [2][512]
    float* hb0   = smem + 1024;                // [128] batch row 0 h
    float* hb1   = smem + 1152;                // [128] batch row 1 h
    float2* Wsp  = (float2*)(smem + 1280);     // [512][29] packed weight k-pairs

    int tid = threadIdx.x;                     // 0..255
    int b0 = blockIdx.x * 2;
    int j1 = tid + 256;

    // stage smem weights (packed pairs, padded rows)
    for (int i = tid; i < GDIM * KSP; i += 256) {
        int j = i / KSP, p = i - j * KSP;
        Wsp[j * WSTRIDE + p] = g_WTp[i];
    }
    // register weights: 36 packed pairs per column covering k in [0,72)
    u64 wregA[KREG / 2], wregB[KREG / 2];
    #pragma unroll
    for (int p = 0; p < KREG / 2; p++) {
        wregA[p] = pack2(g_WT[(2 * p) * GDIM + tid], g_WT[(2 * p + 1) * GDIM + tid]);
        wregB[p] = pack2(g_WT[(2 * p) * GDIM + j1],  g_WT[(2 * p + 1) * GDIM + j1]);
    }

    if (tid < 128) { hb0[tid] = 0.f; hb1[tid] = 0.f; }

    float wt0 = w_time[0], wt1 = w_time[1], wt2 = w_time[2];
    float cc = 0.f, hs0 = 0.f, hs1 = 0.f, cs0 = 0.f, cs1 = 0.f;
    __syncthreads();

    // four G streams: (batch row, column) = (0,j0),(0,j1),(1,j0),(1,j1)
    const float* G00 = g_G + (size_t)b0 * SEQ * GDIM + tid;
    const float* G01 = G00 + 256;
    const float* G10 = g_G + (size_t)(b0 + 1) * SEQ * GDIM + tid;
    const float* G11 = G10 + 256;
    float* hout0 = g_hout + (size_t)b0 * SEQ * HDIM;
    float* hout1 = g_hout + (size_t)(b0 + 1) * SEQ * HDIM;

    const u64* Wrow0 = (const u64*)(Wsp + tid * WSTRIDE);
    const u64* Wrow1 = (const u64*)(Wsp + j1 * WSTRIDE);

    float pre00 = G00[0], pre01 = G01[0], pre10 = G10[0], pre11 = G11[0];

    int slot = 0;
    for (int t = 0; t < SEQ; t++) {
        u64 acc00 = pack2(pre00, 0.f);
        u64 acc01 = pack2(pre01, 0.f);
        u64 acc10 = pack2(pre10, 0.f);
        u64 acc11 = pack2(pre11, 0.f);
        int tn = (t + 1 < SEQ) ? (t + 1) : t;      // prefetch next step's G
        pre00 = G00[(size_t)tn * GDIM];
        pre01 = G01[(size_t)tn * GDIM];
        pre10 = G10[(size_t)tn * GDIM];
        pre11 = G11[(size_t)tn * GDIM];

        const ulonglong2* H0 = (const ulonglong2*)hb0;
        const ulonglong2* H1 = (const ulonglong2*)hb1;
        #pragma unroll
        for (int q = 0; q < 32; q++) {             // 4 k per q (2 pairs)
            ulonglong2 h0 = H0[q];
            ulonglong2 h1 = H1[q];
            u64 wA0, wB0, wA1, wB1;
            if (q < KREG / 4) {                    // q < 18: both pairs from regs
                wA0 = wregA[2 * q];     wB0 = wregA[2 * q + 1];
                wA1 = wregB[2 * q];     wB1 = wregB[2 * q + 1];
            } else {                               // smem pairs 2q-36, 2q-35
                wA0 = Wrow0[2 * q - KREG / 2];  wB0 = Wrow0[2 * q - KREG / 2 + 1];
                wA1 = Wrow1[2 * q - KREG / 2];  wB1 = Wrow1[2 * q - KREG / 2 + 1];
            }
            fma2(acc00, wA0, h0.x);
            fma2(acc10, wA0, h1.x);
            fma2(acc01, wA1, h0.x);
            fma2(acc11, wA1, h1.x);
            fma2(acc00, wB0, h0.y);
            fma2(acc10, wB0, h1.y);
            fma2(acc01, wB1, h0.y);
            fma2(acc11, wB1, h1.y);
        }
        float2 a00 = unpack2(acc00), a01 = unpack2(acc01);
        float2 a10 = unpack2(acc10), a11 = unpack2(acc11);
        gates[tid]              = a00.x + a00.y;
        gates[tid + 256]        = a01.x + a01.y;
        gates[GDIM + tid]       = a10.x + a10.y;
        gates[GDIM + tid + 256] = a11.x + a11.y;
        __syncthreads();

        {   // phase B: all 256 threads; thread -> (batch b, hidden k)
            int b = tid >> 7, k = tid & 127;
            const float* gb = gates + b * GDIM;
            float ig = gb[k], fg = gb[HDIM + k], gg = gb[2 * HDIM + k], og = gb[3 * HDIM + k];
            float cn = fmaf(sigf(fg), cc, sigf(ig) * tanh_fast(gg));
            float hn = sigf(og) * tanh_fast(cn);
            float ho, co;
            if (slot == 0)      { hs0 = hn; cs0 = cn; ho = hn; co = cn; }
            else if (slot == 1) { hs1 = hn; cs1 = cn; ho = hn; co = cn; }
            else {
                ho = wt0 * hs0 + wt1 * hs1 + wt2 * hn;
                co = wt0 * cs0 + wt1 * cs1 + wt2 * cn;
            }
            cc = co;
            (b ? hb1 : hb0)[k] = ho;
            (b ? hout1 : hout0)[(size_t)t * HDIM + k] = ho;
        }
        slot = (slot == 2) ? 0 : slot + 1;
        __syncthreads();
    }
}

// ---------------- kernel 3: logits = hout @ W_br^T + b_br, then log_softmax ----------------
// one warp per (b,s) row; each lane owns 4 h values via a single LDG.128.
__global__ void __launch_bounds__(256) logits_kernel(const float* __restrict__ W_br,
                                                     const float* __restrict__ b_br,
                                                     float* __restrict__ out) {
    __shared__ float wbr[4 * HDIM];
    __shared__ float bb[4];
    int tid = threadIdx.x;
    for (int i = tid; i < 4 * HDIM; i += 256) wbr[i] = W_br[i];
    if (tid < 4) bb[tid] = b_br[tid];
    __syncthreads();

    int warp = tid >> 5, lane = tid & 31;
    size_t row = (size_t)blockIdx.x * 8 + warp;
    float4 hv = *(const float4*)(g_hout + row * HDIM + lane * 4);

    float p[4];
    #pragma unroll
    for (int o = 0; o < 4; o++) {
        float4 w = *(const float4*)&wbr[o * HDIM + lane * 4];
        p[o] = fmaf(hv.x, w.x, fmaf(hv.y, w.y, fmaf(hv.z, w.z, hv.w * w.w)));
    }
    #pragma unroll
    for (int off = 16; off; off >>= 1) {
        #pragma unroll
        for (int o = 0; o < 4; o++) p[o] += __shfl_xor_sync(0xffffffffu, p[o], off);
    }
    if (lane == 0) {
        float x0 = p[0] + bb[0], x1 = p[1] + bb[1], x2 = p[2] + bb[2], x3 = p[3] + bb[3];
        float m = fmaxf(fmaxf(x0, x1), fmaxf(x2, x3));
        float s = __expf(x0 - m) + __expf(x1 - m) + __expf(x2 - m) + __expf(x3 - m);
        float l = __logf(s);
        *(float4*)(out + row * 4) = make_float4(x0 - m - l, x1 - m - l, x2 - m - l, x3 - m - l);
    }
}

// ---------------- launch ----------------
extern "C" void kernel_launch(void* const* d_in, const int* in_sizes, int n_in,
                              void* d_out, int out_size) {
    const float* x      = (const float*)d_in[0];
    const float* W_in   = (const float*)d_in[1];
    const float* b_in   = (const float*)d_in[2];
    const float* W_ih   = (const float*)d_in[3];
    const float* b_ih   = (const float*)d_in[4];
    const float* W_hh   = (const float*)d_in[5];
    const float* b_hh   = (const float*)d_in[6];
    const float* w_time = (const float*)d_in[7];
    const float* W_br   = (const float*)d_in[8];
    const float* b_br   = (const float*)d_in[9];
    float* out = (float*)d_out;

    combine_kernel<<<GDIM, 128>>>(W_in, b_in, W_ih, b_ih, W_hh, b_hh);
    gemm_kernel<<<dim3(4, 1024), 256>>>(x);

    // gates(1024) + hb0/hb1(256) + Wsp(512*29 float2 = 29696 floats)
    size_t shmem = (size_t)(1024 + 256 + GDIM * WSTRIDE * 2) * sizeof(float);  // 123904 B
    cudaFuncSetAttribute(lstm_kernel, cudaFuncAttributeMaxDynamicSharedMemorySize, (int)shmem);
    lstm_kernel<<<BATCH / 2, 256, shmem>>>(w_time);

    logits_kernel<<<(BATCH * SEQ) / 8, 256>>>(W_br, b_br, out);
}

// round 7
// speedup vs baseline: 1.0491x; 1.0491x over previous
#include <cuda_runtime.h>
#include <cstdint>
#include <cstddef>

#define HDIM   128
#define GDIM   512      // 4*H
#define BATCH  256
#define SEQ    512
#define DIN    80
#define EMB    256
#define KREG   64       // k-rows of W_hh^T register-resident per column (32 f32x2 pairs)
#define KSP    32       // remaining (128-64)/2 = 32 k-pairs per column in shared memory
#define WSTRIDE 33      // float2 row stride (66 words: phase-banks conflict-free LDS.64)
#define NSEG   4
#define TSEG   128      // steps per lstm segment launch

typedef unsigned long long u64;

// ---------------- device scratch (no allocations allowed) ----------------
__device__ float g_G[(size_t)BATCH * SEQ * GDIM];    // gate pre-activations (input part)
__device__ float g_hout[(size_t)BATCH * SEQ * HDIM]; // per-step h_out
__device__ float g_Wc[GDIM * DIN];                   // fused  W_ih @ W_in   [512][80]
__device__ float g_bc[GDIM];                         // fused  W_ih@b_in + b_ih + b_hh
__device__ float2 g_WTrp[(KREG / 2) * GDIM];         // reg-weight pairs: [p][j] = (WT[2p][j],WT[2p+1][j])
__device__ float2 g_WTp[GDIM * KSP];                 // smem-weight pairs (k in [KREG,128)) per column j
// LSTM state carried between segment launches
__device__ float g_hst[BATCH * HDIM];
__device__ float g_cst[BATCH * HDIM];
__device__ float g_hs0[BATCH * HDIM];
__device__ float g_hs1[BATCH * HDIM];
__device__ float g_cs0[BATCH * HDIM];
__device__ float g_cs1[BATCH * HDIM];

// ---------------- f32x2 helpers ----------------
__device__ __forceinline__ void fma2(u64& d, u64 a, u64 b) {
    asm("fma.rn.f32x2 %0, %1, %2, %0;" : "+l"(d) : "l"(a), "l"(b));
}
__device__ __forceinline__ u64 pack2(float lo, float hi) {
    u64 r; asm("mov.b64 %0, {%1, %2};" : "=l"(r) : "f"(lo), "f"(hi)); return r;
}
__device__ __forceinline__ u64 dup2(float x) {
    u64 r; asm("mov.b64 %0, {%1, %1};" : "=l"(r) : "f"(x)); return r;
}
__device__ __forceinline__ float2 unpack2(u64 v) {
    float2 r; asm("mov.b64 {%0, %1}, %2;" : "=f"(r.x), "=f"(r.y) : "l"(v)); return r;
}

// ---------------- math helpers (clamp-free; saturation via inf->rcp->0) ----------------
__device__ __forceinline__ float sigf(float x) {
    return __fdividef(1.0f, 1.0f + __expf(-x));
}
__device__ __forceinline__ float tanh_fast(float x) {
    return 1.0f - __fdividef(2.0f, __expf(2.0f * x) + 1.0f);
}

// ---------------- kernel 0: fold W_in into W_ih, pack W_hh^T ----------------
__global__ void combine_kernel(const float* __restrict__ W_in, const float* __restrict__ b_in,
                               const float* __restrict__ W_ih, const float* __restrict__ b_ih,
                               const float* __restrict__ W_hh, const float* __restrict__ b_hh) {
    __shared__ float wih[EMB];
    int j = blockIdx.x;           // 0..511
    int tid = threadIdx.x;        // 128 threads (= k index)
    for (int e = tid; e < EMB; e += 128) wih[e] = W_ih[j * EMB + e];
    if (!(tid & 1)) {
        float2 wp = make_float2(W_hh[j * HDIM + tid], W_hh[j * HDIM + tid + 1]);
        if (tid < KREG) g_WTrp[(tid >> 1) * GDIM + j] = wp;           // register part
        else            g_WTp[j * KSP + ((tid - KREG) >> 1)] = wp;    // smem part
    }
    __syncthreads();
    if (tid < DIN) {
        float s = 0.f;
        #pragma unroll 8
        for (int e = 0; e < EMB; e++) s = fmaf(wih[e], W_in[e * DIN + tid], s);
        g_Wc[j * DIN + tid] = s;
    }
    if (tid == 96) {
        float s = b_ih[j] + b_hh[j];
        #pragma unroll 8
        for (int e = 0; e < EMB; e++) s = fmaf(wih[e], b_in[e], s);
        g_bc[j] = s;
    }
}

// ---------------- kernel 1: G[m][j] = x[m][:] . Wc[j][:] + bc[j] ----------------
// M = 131072, N = 512, K = 80. BM=BN=128, 256 threads, 8x8 tile, f32x2 packed.
// Tile loads are float4-vectorized (5 LDG.128 per thread per k-tile).
__global__ void __launch_bounds__(256, 2) gemm_kernel(const float* __restrict__ x) {
    __shared__ float As[40][132];  // x tile transposed   As[k][m']
    __shared__ float Bs[40][132];  // Wc tile transposed  Bs[k][n']
    __shared__ float bcs[128];

    int tid = threadIdx.x;
    int n0 = blockIdx.x * 128;
    int m0 = blockIdx.y * 128;
    if (tid < 128) bcs[tid] = g_bc[n0 + tid];
    int tr = tid >> 4, tc = tid & 15;

    u64 acc[8][4];
    #pragma unroll
    for (int i = 0; i < 8; i++)
        #pragma unroll
        for (int j = 0; j < 4; j++) acc[i][j] = 0ull;

    for (int kt = 0; kt < 2; kt++) {
        #pragma unroll
        for (int r = 0; r < 5; r++) {
            int idx = tid + r * 256;      // 0..1279
            int row = idx / 10;
            int c4  = idx - row * 10;     // 0..9 -> 4 k's each
            float4 xa = *(const float4*)&x[(size_t)(m0 + row) * DIN + kt * 40 + c4 * 4];
            float4 wb = *(const float4*)&g_Wc[(n0 + row) * DIN + kt * 40 + c4 * 4];
            As[c4 * 4 + 0][row] = xa.x; As[c4 * 4 + 1][row] = xa.y;
            As[c4 * 4 + 2][row] = xa.z; As[c4 * 4 + 3][row] = xa.w;
            Bs[c4 * 4 + 0][row] = wb.x; Bs[c4 * 4 + 1][row] = wb.y;
            Bs[c4 * 4 + 2][row] = wb.z; Bs[c4 * 4 + 3][row] = wb.w;
        }
        __syncthreads();
        #pragma unroll 4
        for (int k = 0; k < 40; k++) {
            float4 a0 = *(const float4*)&As[k][tr * 8];
            float4 a1 = *(const float4*)&As[k][tr * 8 + 4];
            float4 b0 = *(const float4*)&Bs[k][tc * 8];
            float4 b1 = *(const float4*)&Bs[k][tc * 8 + 4];
            u64 ap[8] = {dup2(a0.x), dup2(a0.y), dup2(a0.z), dup2(a0.w),
                         dup2(a1.x), dup2(a1.y), dup2(a1.z), dup2(a1.w)};
            u64 bp[4] = {pack2(b0.x, b0.y), pack2(b0.z, b0.w),
                         pack2(b1.x, b1.y), pack2(b1.z, b1.w)};
            #pragma unroll
            for (int i = 0; i < 8; i++)
                #pragma unroll
                for (int j = 0; j < 4; j++)
                    fma2(acc[i][j], ap[i], bp[j]);
        }
        __syncthreads();
    }

    float bc0 = bcs[tc * 8 + 0], bc1 = bcs[tc * 8 + 1], bc2 = bcs[tc * 8 + 2], bc3 = bcs[tc * 8 + 3];
    float bc4 = bcs[tc * 8 + 4], bc5 = bcs[tc * 8 + 5], bc6 = bcs[tc * 8 + 6], bc7 = bcs[tc * 8 + 7];
    #pragma unroll
    for (int i = 0; i < 8; i++) {
        float* orow = g_G + (size_t)(m0 + tr * 8 + i) * GDIM + n0 + tc * 8;
        float2 v0 = unpack2(acc[i][0]), v1 = unpack2(acc[i][1]);
        float2 v2 = unpack2(acc[i][2]), v3 = unpack2(acc[i][3]);
        *(float4*)orow       = make_float4(v0.x + bc0, v0.y + bc1, v1.x + bc2, v1.y + bc3);
        *(float4*)(orow + 4) = make_float4(v2.x + bc4, v2.y + bc5, v3.x + bc6, v3.y + bc7);
    }
}

// ---------------- kernel 2: LSTM recurrence segment [t0, t0+TSEG) ----------------
// 128 blocks x 256 threads; block owns batch rows (2b, 2b+1).
// Thread tid owns gate columns j0=tid, j1=tid+256 for both rows (4 f32x2 accs).
// Per column: k in [0,64) as 32 f32x2 register pairs, k in [64,128) as 32
// float2 pairs in smem (stride-33 rows, conflict-free LDS.64).
// LSTM state (h, c, pooling slots) round-trips through device globals between
// segment launches; slot phase derives from t0.
__global__ void __launch_bounds__(256, 1) lstm_kernel(const float* __restrict__ w_time, int t0) {
    extern __shared__ float smem[];
    float* gates = smem;                       // [2][512]
    float* hb0   = smem + 1024;                // [128] batch row 0 h
    float* hb1   = smem + 1152;                // [128] batch row 1 h
    float2* Wsp  = (float2*)(smem + 1280);     // [512][33] packed weight k-pairs

    int tid = threadIdx.x;                     // 0..255
    int b0 = blockIdx.x * 2;
    int j1 = tid + 256;

    // stage smem weights (packed pairs, padded rows)
    for (int i = tid; i < GDIM * KSP; i += 256) {
        int j = i / KSP, p = i - j * KSP;
        Wsp[j * WSTRIDE + p] = g_WTp[i];
    }
    // register weights: 32 pairs per column, coalesced LDG.64
    u64 wregA[KREG / 2], wregB[KREG / 2];
    #pragma unroll
    for (int p = 0; p < KREG / 2; p++) {
        float2 a = g_WTrp[p * GDIM + tid];
        float2 b = g_WTrp[p * GDIM + j1];
        wregA[p] = pack2(a.x, a.y);
        wregB[p] = pack2(b.x, b.y);
    }

    // load carried state (zeros at t0 == 0)
    int sb = tid >> 7, sk = tid & 127;
    int sidx = (b0 + sb) * HDIM + sk;
    float cc, hs0, hs1, cs0, cs1;
    {
        float hld;
        if (t0 == 0) { hld = 0.f; cc = 0.f; hs0 = hs1 = cs0 = cs1 = 0.f; }
        else {
            hld = g_hst[sidx]; cc = g_cst[sidx];
            hs0 = g_hs0[sidx]; hs1 = g_hs1[sidx];
            cs0 = g_cs0[sidx]; cs1 = g_cs1[sidx];
        }
        (sb ? hb1 : hb0)[sk] = hld;
    }

    float wt0 = w_time[0], wt1 = w_time[1], wt2 = w_time[2];
    __syncthreads();

    // four G streams: (batch row, column) = (0,j0),(0,j1),(1,j0),(1,j1)
    const float* G00 = g_G + (size_t)b0 * SEQ * GDIM + tid;
    const float* G01 = G00 + 256;
    const float* G10 = g_G + (size_t)(b0 + 1) * SEQ * GDIM + tid;
    const float* G11 = G10 + 256;
    float* hout0 = g_hout + (size_t)b0 * SEQ * HDIM;
    float* hout1 = g_hout + (size_t)(b0 + 1) * SEQ * HDIM;

    const u64* Wrow0 = (const u64*)(Wsp + tid * WSTRIDE);
    const u64* Wrow1 = (const u64*)(Wsp + j1 * WSTRIDE);

    float pre00 = G00[(size_t)t0 * GDIM], pre01 = G01[(size_t)t0 * GDIM];
    float pre10 = G10[(size_t)t0 * GDIM], pre11 = G11[(size_t)t0 * GDIM];

    int slot = t0 % 3;
    for (int t = 0; t < TSEG; t++) {
        int tg = t0 + t;
        u64 acc00 = pack2(pre00, 0.f);
        u64 acc01 = pack2(pre01, 0.f);
        u64 acc10 = pack2(pre10, 0.f);
        u64 acc11 = pack2(pre11, 0.f);
        int tn = (tg + 1 < SEQ) ? (tg + 1) : tg;   // prefetch next step's G
        pre00 = G00[(size_t)tn * GDIM];
        pre01 = G01[(size_t)tn * GDIM];
        pre10 = G10[(size_t)tn * GDIM];
        pre11 = G11[(size_t)tn * GDIM];

        const ulonglong2* H0 = (const ulonglong2*)hb0;
        const ulonglong2* H1 = (const ulonglong2*)hb1;
        #pragma unroll
        for (int q = 0; q < 32; q++) {             // 4 k per q (2 pairs)
            ulonglong2 h0 = H0[q];
            ulonglong2 h1 = H1[q];
            u64 wA0, wB0, wA1, wB1;
            if (q < KREG / 4) {                    // q < 16: pairs from regs
                wA0 = wregA[2 * q];     wB0 = wregA[2 * q + 1];
                wA1 = wregB[2 * q];     wB1 = wregB[2 * q + 1];
            } else {                               // smem pairs 2q-32, 2q-31
                wA0 = Wrow0[2 * q - KREG / 2];  wB0 = Wrow0[2 * q - KREG / 2 + 1];
                wA1 = Wrow1[2 * q - KREG / 2];  wB1 = Wrow1[2 * q - KREG / 2 + 1];
            }
            fma2(acc00, wA0, h0.x);
            fma2(acc10, wA0, h1.x);
            fma2(acc01, wA1, h0.x);
            fma2(acc11, wA1, h1.x);
            fma2(acc00, wB0, h0.y);
            fma2(acc10, wB0, h1.y);
            fma2(acc01, wB1, h0.y);
            fma2(acc11, wB1, h1.y);
        }
        float2 a00 = unpack2(acc00), a01 = unpack2(acc01);
        float2 a10 = unpack2(acc10), a11 = unpack2(acc11);
        gates[tid]              = a00.x + a00.y;
        gates[tid + 256]        = a01.x + a01.y;
        gates[GDIM + tid]       = a10.x + a10.y;
        gates[GDIM + tid + 256] = a11.x + a11.y;
        __syncthreads();

        {   // phase B: all 256 threads; thread -> (batch sb, hidden sk)
            const float* gb = gates + sb * GDIM;
            float ig = gb[sk], fg = gb[HDIM + sk], gg = gb[2 * HDIM + sk], og = gb[3 * HDIM + sk];
            float cn = fmaf(sigf(fg), cc, sigf(ig) * tanh_fast(gg));
            float hn = sigf(og) * tanh_fast(cn);
            float ho, co;
            if (slot == 0)      { hs0 = hn; cs0 = cn; ho = hn; co = cn; }
            else if (slot == 1) { hs1 = hn; cs1 = cn; ho = hn; co = cn; }
            else {
                ho = wt0 * hs0 + wt1 * hs1 + wt2 * hn;
                co = wt0 * cs0 + wt1 * cs1 + wt2 * cn;
            }
            cc = co;
            (sb ? hb1 : hb0)[sk] = ho;
            (sb ? hout1 : hout0)[(size_t)tg * HDIM + sk] = ho;
        }
        slot = (slot == 2) ? 0 : slot + 1;
        __syncthreads();
    }

    // store carried state
    g_hst[sidx] = (sb ? hb1 : hb0)[sk];
    g_cst[sidx] = cc;
    g_hs0[sidx] = hs0; g_hs1[sidx] = hs1;
    g_cs0[sidx] = cs0; g_cs1[sidx] = cs1;
}

// ---------------- kernel 3: logits = hout @ W_br^T + b_br, then log_softmax ----------------
// one warp per (b,s) row; each lane owns 4 h values via a single LDG.128.
__global__ void __launch_bounds__(256) logits_kernel(const float* __restrict__ W_br,
                                                     const float* __restrict__ b_br,
                                                     float* __restrict__ out) {
    __shared__ float wbr[4 * HDIM];
    __shared__ float bb[4];
    int tid = threadIdx.x;
    for (int i = tid; i < 4 * HDIM; i += 256) wbr[i] = W_br[i];
    if (tid < 4) bb[tid] = b_br[tid];
    __syncthreads();

    int warp = tid >> 5, lane = tid & 31;
    size_t row = (size_t)blockIdx.x * 8 + warp;
    float4 hv = *(const float4*)(g_hout + row * HDIM + lane * 4);

    float p[4];
    #pragma unroll
    for (int o = 0; o < 4; o++) {
        float4 w = *(const float4*)&wbr[o * HDIM + lane * 4];
        p[o] = fmaf(hv.x, w.x, fmaf(hv.y, w.y, fmaf(hv.z, w.z, hv.w * w.w)));
    }
    #pragma unroll
    for (int off = 16; off; off >>= 1) {
        #pragma unroll
        for (int o = 0; o < 4; o++) p[o] += __shfl_xor_sync(0xffffffffu, p[o], off);
    }
    if (lane == 0) {
        float x0 = p[0] + bb[0], x1 = p[1] + bb[1], x2 = p[2] + bb[2], x3 = p[3] + bb[3];
        float m = fmaxf(fmaxf(x0, x1), fmaxf(x2, x3));
        float s = __expf(x0 - m) + __expf(x1 - m) + __expf(x2 - m) + __expf(x3 - m);
        float l = __logf(s);
        *(float4*)(out + row * 4) = make_float4(x0 - m - l, x1 - m - l, x2 - m - l, x3 - m - l);
    }
}

// ---------------- launch ----------------
extern "C" void kernel_launch(void* const* d_in, const int* in_sizes, int n_in,
                              void* d_out, int out_size) {
    const float* x      = (const float*)d_in[0];
    const float* W_in   = (const float*)d_in[1];
    const float* b_in   = (const float*)d_in[2];
    const float* W_ih   = (const float*)d_in[3];
    const float* b_ih   = (const float*)d_in[4];
    const float* W_hh   = (const float*)d_in[5];
    const float* b_hh   = (const float*)d_in[6];
    const float* w_time = (const float*)d_in[7];
    const float* W_br   = (const float*)d_in[8];
    const float* b_br   = (const float*)d_in[9];
    float* out = (float*)d_out;

    combine_kernel<<<GDIM, 128>>>(W_in, b_in, W_ih, b_ih, W_hh, b_hh);
    gemm_kernel<<<dim3(4, 1024), 256>>>(x);

    // gates(1024) + hb0/hb1(256) + Wsp(512*33 float2 = 33792 floats)
    size_t shmem = (size_t)(1024 + 256 + GDIM * WSTRIDE * 2) * sizeof(float);  // 140288 B
    cudaFuncSetAttribute(lstm_kernel, cudaFuncAttributeMaxDynamicSharedMemorySize, (int)shmem);
    for (int s = 0; s < NSEG; s++)
        lstm_kernel<<<BATCH / 2, 256, shmem>>>(w_time, s * TSEG);

    logits_kernel<<<(BATCH * SEQ) / 8, 256>>>(W_br, b_br, out);
}

// round 8
// speedup vs baseline: 1.0762x; 1.0258x over previous
#include <cuda_runtime.h>
#include <cstdint>
#include <cstddef>

#define HDIM   128
#define GDIM   512      // 4*H
#define BATCH  256
#define SEQ    512
#define DIN    80
#define EMB    256
#define KREGP  18       // k-PAIRS register-resident per column (k in [0,36))
#define KSP    46       // k-pairs per column in shared memory (k in [36,128))
#define WSTRIDE 46      // float2 row stride: 368B = 23 16B-chunks, coprime 8 -> conflict-free LDS.128
#define NSEG   4
#define TSEG   128      // steps per lstm segment launch
#define LOG2E  1.4426950408889634f
#define C2LOG2E 2.8853900817779268f

typedef unsigned long long u64;

// ---------------- device scratch (no allocations allowed) ----------------
__device__ float g_G[(size_t)BATCH * SEQ * GDIM];    // gate pre-activations (input part, prescaled)
__device__ float g_hout[(size_t)BATCH * SEQ * HDIM]; // per-step h_out
__device__ float g_Wc[GDIM * DIN];                   // fused + prescaled  W_ih @ W_in
__device__ float g_bc[GDIM];                         // fused + prescaled  bias
__device__ float2 g_WTrp[KREGP * GDIM];              // reg-weight pairs: [p][j] (prescaled)
__device__ float2 g_WTp[GDIM * KSP];                 // smem-weight pairs: [j][p-KREGP] (prescaled)
// LSTM state carried between segment launches
__device__ float g_hst[BATCH * HDIM];
__device__ float g_cst[BATCH * HDIM];
__device__ float g_hsA[BATCH * HDIM];
__device__ float g_hsB[BATCH * HDIM];
__device__ float g_csA[BATCH * HDIM];
__device__ float g_csB[BATCH * HDIM];

// ---------------- f32x2 helpers ----------------
__device__ __forceinline__ void fma2(u64& d, u64 a, u64 b) {
    asm("fma.rn.f32x2 %0, %1, %2, %0;" : "+l"(d) : "l"(a), "l"(b));
}
__device__ __forceinline__ u64 pack2(float lo, float hi) {
    u64 r; asm("mov.b64 %0, {%1, %2};" : "=l"(r) : "f"(lo), "f"(hi)); return r;
}
__device__ __forceinline__ u64 dup2(float x) {
    u64 r; asm("mov.b64 %0, {%1, %1};" : "=l"(r) : "f"(x)); return r;
}
__device__ __forceinline__ float2 unpack2(u64 v) {
    float2 r; asm("mov.b64 {%0, %1}, %2;" : "=f"(r.x), "=f"(r.y) : "l"(v)); return r;
}

// ---------------- fast activation primitives (inputs prescaled by log2e) ----------------
__device__ __forceinline__ float ex2f(float x) {
    float r; asm("ex2.approx.f32 %0, %1;" : "=f"(r) : "f"(x)); return r;
}
__device__ __forceinline__ float rcpf(float x) {
    float r; asm("rcp.approx.f32 %0, %1;" : "=f"(r) : "f"(x)); return r;
}
// sigmoid(z) where g = log2e*z: 1/(1+2^-g). Saturation safe: ex2->inf -> rcp->0.
__device__ __forceinline__ float sig_p(float g) { return rcpf(1.0f + ex2f(-g)); }
// tanh(z) where g = 2*log2e*z: 1 - 2/(2^g+1)
__device__ __forceinline__ float tanh_p(float g) { return fmaf(-2.0f, rcpf(ex2f(g) + 1.0f), 1.0f); }

// ---------------- kernel 0: fold W_in into W_ih, prescale, pack W_hh^T ----------------
__global__ void combine_kernel(const float* __restrict__ W_in, const float* __restrict__ b_in,
                               const float* __restrict__ W_ih, const float* __restrict__ b_ih,
                               const float* __restrict__ W_hh, const float* __restrict__ b_hh) {
    __shared__ float wih[EMB];
    int j = blockIdx.x;           // 0..511
    int tid = threadIdx.x;        // 128 threads (= k index)
    float s = ((j >> 7) == 2) ? C2LOG2E : LOG2E;   // g-gate rows get 2*log2e
    for (int e = tid; e < EMB; e += 128) wih[e] = W_ih[j * EMB + e];
    if (!(tid & 1)) {
        float2 wp = make_float2(s * W_hh[j * HDIM + tid], s * W_hh[j * HDIM + tid + 1]);
        int p = tid >> 1;
        if (p < KREGP) g_WTrp[p * GDIM + j] = wp;           // register part
        else           g_WTp[j * KSP + (p - KREGP)] = wp;   // smem part
    }
    __syncthreads();
    if (tid < DIN) {
        float acc = 0.f;
        #pragma unroll 8
        for (int e = 0; e < EMB; e++) acc = fmaf(wih[e], W_in[e * DIN + tid], acc);
        g_Wc[j * DIN + tid] = s * acc;
    }
    if (tid == 96) {
        float acc = b_ih[j] + b_hh[j];
        #pragma unroll 8
        for (int e = 0; e < EMB; e++) acc = fmaf(wih[e], b_in[e], acc);
        g_bc[j] = s * acc;
    }
}

// ---------------- kernel 1: G[m][j] = x[m][:] . Wc[j][:] + bc[j] ----------------
// M = 131072, N = 512, K = 80. BM=BN=128, 256 threads, 8x8 tile, f32x2 packed.
__global__ void __launch_bounds__(256, 2) gemm_kernel(const float* __restrict__ x) {
    __shared__ float As[40][132];
    __shared__ float Bs[40][132];
    __shared__ float bcs[128];

    int tid = threadIdx.x;
    int n0 = blockIdx.x * 128;
    int m0 = blockIdx.y * 128;
    if (tid < 128) bcs[tid] = g_bc[n0 + tid];
    int tr = tid >> 4, tc = tid & 15;

    u64 acc[8][4];
    #pragma unroll
    for (int i = 0; i < 8; i++)
        #pragma unroll
        for (int j = 0; j < 4; j++) acc[i][j] = 0ull;

    for (int kt = 0; kt < 2; kt++) {
        #pragma unroll
        for (int r = 0; r < 5; r++) {
            int idx = tid + r * 256;
            int row = idx / 10;
            int c4  = idx - row * 10;
            float4 xa = *(const float4*)&x[(size_t)(m0 + row) * DIN + kt * 40 + c4 * 4];
            float4 wb = *(const float4*)&g_Wc[(n0 + row) * DIN + kt * 40 + c4 * 4];
            As[c4 * 4 + 0][row] = xa.x; As[c4 * 4 + 1][row] = xa.y;
            As[c4 * 4 + 2][row] = xa.z; As[c4 * 4 + 3][row] = xa.w;
            Bs[c4 * 4 + 0][row] = wb.x; Bs[c4 * 4 + 1][row] = wb.y;
            Bs[c4 * 4 + 2][row] = wb.z; Bs[c4 * 4 + 3][row] = wb.w;
        }
        __syncthreads();
        #pragma unroll 4
        for (int k = 0; k < 40; k++) {
            float4 a0 = *(const float4*)&As[k][tr * 8];
            float4 a1 = *(const float4*)&As[k][tr * 8 + 4];
            float4 b0 = *(const float4*)&Bs[k][tc * 8];
            float4 b1 = *(const float4*)&Bs[k][tc * 8 + 4];
            u64 ap[8] = {dup2(a0.x), dup2(a0.y), dup2(a0.z), dup2(a0.w),
                         dup2(a1.x), dup2(a1.y), dup2(a1.z), dup2(a1.w)};
            u64 bp[4] = {pack2(b0.x, b0.y), pack2(b0.z, b0.w),
                         pack2(b1.x, b1.y), pack2(b1.z, b1.w)};
            #pragma unroll
            for (int i = 0; i < 8; i++)
                #pragma unroll
                for (int j = 0; j < 4; j++)
                    fma2(acc[i][j], ap[i], bp[j]);
        }
        __syncthreads();
    }

    float bc0 = bcs[tc * 8 + 0], bc1 = bcs[tc * 8 + 1], bc2 = bcs[tc * 8 + 2], bc3 = bcs[tc * 8 + 3];
    float bc4 = bcs[tc * 8 + 4], bc5 = bcs[tc * 8 + 5], bc6 = bcs[tc * 8 + 6], bc7 = bcs[tc * 8 + 7];
    #pragma unroll
    for (int i = 0; i < 8; i++) {
        float* orow = g_G + (size_t)(m0 + tr * 8 + i) * GDIM + n0 + tc * 8;
        float2 v0 = unpack2(acc[i][0]), v1 = unpack2(acc[i][1]);
        float2 v2 = unpack2(acc[i][2]), v3 = unpack2(acc[i][3]);
        *(float4*)orow       = make_float4(v0.x + bc0, v0.y + bc1, v1.x + bc2, v1.y + bc3);
        *(float4*)(orow + 4) = make_float4(v2.x + bc4, v2.y + bc5, v3.x + bc6, v3.y + bc7);
    }
}

// ---------------- kernel 2: LSTM recurrence segment, one barrier per step ----------------
// 128 blocks x 128 threads; block owns batch rows (2b, 2b+1).
// Thread sk owns hidden unit sk: computes all 4 gate dots (cols sk+128m) for
// BOTH rows (8 f32x2 accumulators), then runs its own activation chains --
// gates never touch smem. h is double-buffered in smem -> ONE __syncthreads
// per step. Weights per column: 18 f32x2 pairs in registers, 46 pairs in smem
// (stride-46 float2 rows; LDS.128 reads 2 pairs, conflict-free).
__global__ void __launch_bounds__(128, 1) lstm_kernel(const float* __restrict__ w_time, int t0) {
    extern __shared__ float smem[];
    // hbuf[parity][row][128]
    float* hbuf = smem;                         // 512 floats
    float2* Wsp = (float2*)(smem + 512);        // [512][WSTRIDE]

    int sk = threadIdx.x;                       // 0..127
    int b0 = blockIdx.x * 2;

    // stage smem weights
    for (int i = sk; i < GDIM * KSP; i += 128) {
        int j = i / KSP, p = i - j * KSP;
        Wsp[j * WSTRIDE + p] = g_WTp[i];
    }
    // register weights: 18 pairs x 4 columns
    u64 wreg[4][KREGP];
    #pragma unroll
    for (int m = 0; m < 4; m++) {
        int c = sk + m * 128;
        #pragma unroll
        for (int p = 0; p < KREGP; p++) {
            float2 w = g_WTrp[p * GDIM + c];
            wreg[m][p] = pack2(w.x, w.y);
        }
    }

    // carried state
    int si0 = b0 * HDIM + sk, si1 = si0 + HDIM;
    float cc[2], hsA[2], hsB[2], csA[2], csB[2];
    {
        int par0 = t0 & 1;   // t0 is a multiple of TSEG (even) -> 0, but keep general
        if (t0 == 0) {
            hbuf[par0 * 256 + sk] = 0.f; hbuf[par0 * 256 + 128 + sk] = 0.f;
            cc[0] = cc[1] = 0.f;
            hsA[0] = hsA[1] = hsB[0] = hsB[1] = 0.f;
            csA[0] = csA[1] = csB[0] = csB[1] = 0.f;
        } else {
            hbuf[par0 * 256 + sk]       = g_hst[si0];
            hbuf[par0 * 256 + 128 + sk] = g_hst[si1];
            cc[0] = g_cst[si0]; cc[1] = g_cst[si1];
            hsA[0] = g_hsA[si0]; hsA[1] = g_hsA[si1];
            hsB[0] = g_hsB[si0]; hsB[1] = g_hsB[si1];
            csA[0] = g_csA[si0]; csA[1] = g_csA[si1];
            csB[0] = g_csB[si0]; csB[1] = g_csB[si1];
        }
    }
    float wt0 = w_time[0], wt1 = w_time[1], wt2 = w_time[2];
    __syncthreads();

    const float* Gr0 = g_G + (size_t)b0 * SEQ * GDIM + sk;
    const float* Gr1 = g_G + (size_t)(b0 + 1) * SEQ * GDIM + sk;
    float* ho0 = g_hout + (size_t)b0 * SEQ * HDIM + sk;
    float* ho1 = g_hout + (size_t)(b0 + 1) * SEQ * HDIM + sk;

    const ulonglong2* Wrow[4];
    #pragma unroll
    for (int m = 0; m < 4; m++)
        Wrow[m] = (const ulonglong2*)(Wsp + (sk + m * 128) * WSTRIDE);

    float pre[4][2];
    #pragma unroll
    for (int m = 0; m < 4; m++) {
        pre[m][0] = Gr0[(size_t)t0 * GDIM + m * 128];
        pre[m][1] = Gr1[(size_t)t0 * GDIM + m * 128];
    }

    int slot = t0 % 3;
    for (int t = t0; t < t0 + TSEG; t++) {
        u64 acc[4][2];
        #pragma unroll
        for (int m = 0; m < 4; m++) {
            acc[m][0] = pack2(pre[m][0], 0.f);
            acc[m][1] = pack2(pre[m][1], 0.f);
        }
        int tn = (t + 1 < SEQ) ? (t + 1) : t;   // prefetch next step's G
        #pragma unroll
        for (int m = 0; m < 4; m++) {
            pre[m][0] = Gr0[(size_t)tn * GDIM + m * 128];
            pre[m][1] = Gr1[(size_t)tn * GDIM + m * 128];
        }

        const ulonglong2* H0 = (const ulonglong2*)(hbuf + (t & 1) * 256);
        const ulonglong2* H1 = (const ulonglong2*)(hbuf + (t & 1) * 256 + 128);
        #pragma unroll
        for (int pp = 0; pp < 32; pp++) {        // covers k-pairs 2pp, 2pp+1
            ulonglong2 h0 = H0[pp];
            ulonglong2 h1 = H1[pp];
            #pragma unroll
            for (int m = 0; m < 4; m++) {
                u64 wA, wB;
                if (pp < KREGP / 2) {            // pairs 0..17 from registers
                    wA = wreg[m][2 * pp]; wB = wreg[m][2 * pp + 1];
                } else {                         // pairs 18.. from smem, 2 per LDS.128
                    ulonglong2 wp = Wrow[m][pp - KREGP / 2];
                    wA = wp.x; wB = wp.y;
                }
                fma2(acc[m][0], wA, h0.x);
                fma2(acc[m][1], wA, h1.x);
                fma2(acc[m][0], wB, h0.y);
                fma2(acc[m][1], wB, h1.y);
            }
        }

        // phase B: this thread owns hidden unit sk of both rows
        float g[4][2];
        #pragma unroll
        for (int m = 0; m < 4; m++) {
            float2 v0 = unpack2(acc[m][0]); g[m][0] = v0.x + v0.y;
            float2 v1 = unpack2(acc[m][1]); g[m][1] = v1.x + v1.y;
        }
        float* hw = hbuf + ((t + 1) & 1) * 256;  // write buffer (other parity)
        #pragma unroll
        for (int r = 0; r < 2; r++) {
            float si = sig_p(g[0][r]);
            float sf = sig_p(g[1][r]);
            float tg = tanh_p(g[2][r]);
            float so = sig_p(g[3][r]);
            float cn = fmaf(sf, cc[r], si * tg);
            float tc = tanh_p(C2LOG2E * cn);
            float hn = so * tc;
            float ho_, co_;
            if (slot == 0)      { hsA[r] = hn; csA[r] = cn; ho_ = hn; co_ = cn; }
            else if (slot == 1) { hsB[r] = hn; csB[r] = cn; ho_ = hn; co_ = cn; }
            else {
                ho_ = wt0 * hsA[r] + wt1 * hsB[r] + wt2 * hn;
                co_ = wt0 * csA[r] + wt1 * csB[r] + wt2 * cn;
            }
            cc[r] = co_;
            hw[r * 128 + sk] = ho_;
            (r ? ho1 : ho0)[(size_t)t * HDIM] = ho_;
        }
        slot = (slot == 2) ? 0 : slot + 1;
        __syncthreads();                          // the ONLY barrier per step
    }

    // store carried state (final h lives in buffer parity (t0+TSEG)&1)
    {
        int parE = (t0 + TSEG) & 1;
        g_hst[si0] = hbuf[parE * 256 + sk];
        g_hst[si1] = hbuf[parE * 256 + 128 + sk];
        g_cst[si0] = cc[0]; g_cst[si1] = cc[1];
        g_hsA[si0] = hsA[0]; g_hsA[si1] = hsA[1];
        g_hsB[si0] = hsB[0]; g_hsB[si1] = hsB[1];
        g_csA[si0] = csA[0]; g_csA[si1] = csA[1];
        g_csB[si0] = csB[0]; g_csB[si1] = csB[1];
    }
}

// ---------------- kernel 3: logits = hout @ W_br^T + b_br, then log_softmax ----------------
__global__ void __launch_bounds__(256) logits_kernel(const float* __restrict__ W_br,
                                                     const float* __restrict__ b_br,
                                                     float* __restrict__ out) {
    __shared__ float wbr[4 * HDIM];
    __shared__ float bb[4];
    int tid = threadIdx.x;
    for (int i = tid; i < 4 * HDIM; i += 256) wbr[i] = W_br[i];
    if (tid < 4) bb[tid] = b_br[tid];
    __syncthreads();

    int warp = tid >> 5, lane = tid & 31;
    size_t row = (size_t)blockIdx.x * 8 + warp;
    float4 hv = *(const float4*)(g_hout + row * HDIM + lane * 4);

    float p[4];
    #pragma unroll
    for (int o = 0; o < 4; o++) {
        float4 w = *(const float4*)&wbr[o * HDIM + lane * 4];
        p[o] = fmaf(hv.x, w.x, fmaf(hv.y, w.y, fmaf(hv.z, w.z, hv.w * w.w)));
    }
    #pragma unroll
    for (int off = 16; off; off >>= 1) {
        #pragma unroll
        for (int o = 0; o < 4; o++) p[o] += __shfl_xor_sync(0xffffffffu, p[o], off);
    }
    if (lane == 0) {
        float x0 = p[0] + bb[0], x1 = p[1] + bb[1], x2 = p[2] + bb[2], x3 = p[3] + bb[3];
        float m = fmaxf(fmaxf(x0, x1), fmaxf(x2, x3));
        float s = __expf(x0 - m) + __expf(x1 - m) + __expf(x2 - m) + __expf(x3 - m);
        float l = __logf(s);
        *(float4*)(out + row * 4) = make_float4(x0 - m - l, x1 - m - l, x2 - m - l, x3 - m - l);
    }
}

// ---------------- launch ----------------
extern "C" void kernel_launch(void* const* d_in, const int* in_sizes, int n_in,
                              void* d_out, int out_size) {
    const float* x      = (const float*)d_in[0];
    const float* W_in   = (const float*)d_in[1];
    const float* b_in   = (const float*)d_in[2];
    const float* W_ih   = (const float*)d_in[3];
    const float* b_ih   = (const float*)d_in[4];
    const float* W_hh   = (const float*)d_in[5];
    const float* b_hh   = (const float*)d_in[6];
    const float* w_time = (const float*)d_in[7];
    const float* W_br   = (const float*)d_in[8];
    const float* b_br   = (const float*)d_in[9];
    float* out = (float*)d_out;

    combine_kernel<<<GDIM, 128>>>(W_in, b_in, W_ih, b_ih, W_hh, b_hh);
    gemm_kernel<<<dim3(4, 1024), 256>>>(x);

    // hbuf(512 floats) + Wsp(512 * WSTRIDE float2)
    size_t shmem = 512 * sizeof(float) + (size_t)GDIM * WSTRIDE * sizeof(float2);  // 190464 B
    cudaFuncSetAttribute(lstm_kernel, cudaFuncAttributeMaxDynamicSharedMemorySize, (int)shmem);
    for (int s = 0; s < NSEG; s++)
        lstm_kernel<<<BATCH / 2, 128, shmem>>>(w_time, s * TSEG);

    logits_kernel<<<(BATCH * SEQ) / 8, 256>>>(W_br, b_br, out);
}